// round 7
// baseline (speedup 1.0000x reference)
#include <cuda_runtime.h>
#include <math.h>
#include <stdint.h>

// B=32, N=4096, D=512, K=64
#define Bb 32
#define Nn 4096
#define Dd 512
#define Kk 64
#define NSPLIT 4

__device__ float g_assign[(size_t)Bb * Nn * Kk];            // softmax assignments [b,n,k]
__device__ float g_vpart[(size_t)NSPLIT * Bb * Kk * Dd];    // vlad partials [s,b,k,d]
__device__ float g_asum[Bb * Kk];
__device__ float g_gnormsq[Bb];

__device__ __forceinline__ void mma8(float* c, uint32_t a0, uint32_t a1,
                                     uint32_t a2, uint32_t a3,
                                     uint32_t b0, uint32_t b1) {
    asm volatile(
        "mma.sync.aligned.m16n8k8.row.col.f32.tf32.tf32.f32 "
        "{%0,%1,%2,%3},{%4,%5,%6,%7},{%8,%9},{%0,%1,%2,%3};\n"
        : "+f"(c[0]), "+f"(c[1]), "+f"(c[2]), "+f"(c[3])
        : "r"(a0), "r"(a1), "r"(a2), "r"(a3), "r"(b0), "r"(b1));
}

// ---------------------------------------------------------------------------
__global__ void k0_init() {
    int i = blockIdx.x * 256 + threadIdx.x;
    if (i < Bb * Kk) g_asum[i] = 0.0f;
    if (i < Bb)      g_gnormsq[i] = 0.0f;
}

// ---------------------------------------------------------------------------
// k1: logits = x @ clusters (131072x512 @ 512x64) via tf32 MMA (raw fp32 bits,
// HW truncates to tf32), fused BN(eval) + softmax + assignment + a_sum.
// Block: 256 thr (8 warps), tile 128 rows x 64 cols, K chunk 32.
// ---------------------------------------------------------------------------
__global__ __launch_bounds__(256) void k1_logits_softmax(
    const float* __restrict__ x,
    const float* __restrict__ clusters,
    const float* __restrict__ bnw,
    const float* __restrict__ bnb,
    const float* __restrict__ rm,
    const float* __restrict__ rv)
{
    __shared__ float xs[128][36];   // [row][k], bank = 4*row+k (conflict-free)
    __shared__ float cs[32][72];    // [k][n],  bank = 8*k+n   (conflict-free)
    __shared__ float scf[64], shf[64];
    __shared__ float red[8 * 64];

    const int tid  = threadIdx.x;
    const int lane = tid & 31;
    const int w    = tid >> 5;
    const int la   = lane >> 2;     // 0..7
    const int lb   = lane & 3;      // 0..3
    const int row0 = blockIdx.x * 128;

    const int xr = tid >> 1;              // 0..127
    const int xc = (tid & 1) * 16;        // 0 or 16
    const int cr = tid >> 3;              // 0..31
    const int cc = (tid & 7) * 8;         // 0..56

    const float* xg = x + (size_t)row0 * Dd;

    float acc[8][4];
#pragma unroll
    for (int j = 0; j < 8; j++)
#pragma unroll
        for (int q = 0; q < 4; q++) acc[j][q] = 0.0f;

    float4 px[4];
    float4 pc[2];
#pragma unroll
    for (int q = 0; q < 4; q++)
        px[q] = *(const float4*)&xg[(size_t)xr * Dd + xc + q * 4];
#pragma unroll
    for (int q = 0; q < 2; q++)
        pc[q] = *(const float4*)&clusters[(size_t)cr * Kk + cc + q * 4];

    for (int c = 0; c < 16; c++) {
#pragma unroll
        for (int q = 0; q < 4; q++)
            *(float4*)&xs[xr][xc + q * 4] = px[q];
#pragma unroll
        for (int q = 0; q < 2; q++)
            *(float4*)&cs[cr][cc + q * 4] = pc[q];
        __syncthreads();

        if (c < 15) {
            int d0 = (c + 1) * 32;
#pragma unroll
            for (int q = 0; q < 4; q++)
                px[q] = *(const float4*)&xg[(size_t)xr * Dd + d0 + xc + q * 4];
#pragma unroll
            for (int q = 0; q < 2; q++)
                pc[q] = *(const float4*)&clusters[(size_t)(d0 + cr) * Kk + cc + q * 4];
        }

        const int wr = w * 16 + la;
#pragma unroll
        for (int kk = 0; kk < 4; kk++) {
            uint32_t a0 = __float_as_uint(xs[wr][kk * 8 + lb]);
            uint32_t a1 = __float_as_uint(xs[wr + 8][kk * 8 + lb]);
            uint32_t a2 = __float_as_uint(xs[wr][kk * 8 + 4 + lb]);
            uint32_t a3 = __float_as_uint(xs[wr + 8][kk * 8 + 4 + lb]);
#pragma unroll
            for (int j = 0; j < 8; j++) {
                uint32_t b0 = __float_as_uint(cs[kk * 8 + lb][j * 8 + la]);
                uint32_t b1 = __float_as_uint(cs[kk * 8 + 4 + lb][j * 8 + la]);
                mma8(acc[j], a0, a1, a2, a3, b0, b1);
            }
        }
        __syncthreads();
    }

    // ---- epilogue: BN + softmax + store + a_sum ----
    if (tid < 64) {
        float istd = rsqrtf(rv[tid] + 1e-5f);
        float s = bnw[tid] * istd;
        scf[tid] = s;
        shf[tid] = bnb[tid] - rm[tid] * s;
    }
    __syncthreads();

    float vA[8][2], vB[8][2];
#pragma unroll
    for (int j = 0; j < 8; j++)
#pragma unroll
        for (int e = 0; e < 2; e++) {
            int col = j * 8 + lb * 2 + e;
            float s = scf[col], h = shf[col];
            vA[j][e] = acc[j][e]     * s + h;
            vB[j][e] = acc[j][2 + e] * s + h;
        }

    float mA = -1e30f, mB = -1e30f;
#pragma unroll
    for (int j = 0; j < 8; j++)
#pragma unroll
        for (int e = 0; e < 2; e++) { mA = fmaxf(mA, vA[j][e]); mB = fmaxf(mB, vB[j][e]); }
    mA = fmaxf(mA, __shfl_xor_sync(0xffffffffu, mA, 1));
    mA = fmaxf(mA, __shfl_xor_sync(0xffffffffu, mA, 2));
    mB = fmaxf(mB, __shfl_xor_sync(0xffffffffu, mB, 1));
    mB = fmaxf(mB, __shfl_xor_sync(0xffffffffu, mB, 2));
    float sA = 0.0f, sB = 0.0f;
#pragma unroll
    for (int j = 0; j < 8; j++)
#pragma unroll
        for (int e = 0; e < 2; e++) {
            vA[j][e] = __expf(vA[j][e] - mA); sA += vA[j][e];
            vB[j][e] = __expf(vB[j][e] - mB); sB += vB[j][e];
        }
    sA += __shfl_xor_sync(0xffffffffu, sA, 1);
    sA += __shfl_xor_sync(0xffffffffu, sA, 2);
    sB += __shfl_xor_sync(0xffffffffu, sB, 1);
    sB += __shfl_xor_sync(0xffffffffu, sB, 2);
    float invA = 1.0f / sA, invB = 1.0f / sB;

    float csum[8][2];
    const int grA = row0 + w * 16 + la;
    const int grB = grA + 8;
    float* ag = g_assign;
#pragma unroll
    for (int j = 0; j < 8; j++) {
#pragma unroll
        for (int e = 0; e < 2; e++) {
            vA[j][e] *= invA;
            vB[j][e] *= invB;
            csum[j][e] = vA[j][e] + vB[j][e];
        }
        *(float2*)&ag[(size_t)grA * Kk + j * 8 + lb * 2] = make_float2(vA[j][0], vA[j][1]);
        *(float2*)&ag[(size_t)grB * Kk + j * 8 + lb * 2] = make_float2(vB[j][0], vB[j][1]);
    }

#pragma unroll
    for (int j = 0; j < 8; j++)
#pragma unroll
        for (int e = 0; e < 2; e++) {
            csum[j][e] += __shfl_xor_sync(0xffffffffu, csum[j][e], 4);
            csum[j][e] += __shfl_xor_sync(0xffffffffu, csum[j][e], 8);
            csum[j][e] += __shfl_xor_sync(0xffffffffu, csum[j][e], 16);
        }
    if (la == 0) {
#pragma unroll
        for (int j = 0; j < 8; j++)
#pragma unroll
            for (int e = 0; e < 2; e++)
                red[w * 64 + j * 8 + lb * 2 + e] = csum[j][e];
    }
    __syncthreads();
    if (tid < 64) {
        float s = 0.0f;
#pragma unroll
        for (int q = 0; q < 8; q++) s += red[q * 64 + tid];
        atomicAdd(&g_asum[(row0 >> 12) * Kk + tid], s);
    }
}

// ---------------------------------------------------------------------------
// k2: vlad partials: vpart[s,b,k,d] = sum_{n in split s} x[b,n,d]*assign[b,n,k]
// via tf32 MMA (raw fp32 bits). A = x^T [d][n] in smem, B = assign [n][k].
// Block: 256 thr (8 warps), tile d=128 x k=64, n-chunk 32, 32 chunks/block.
// Grid (4 d-tiles, 32 b, 4 n-splits) = 512 blocks.
// ---------------------------------------------------------------------------
__global__ __launch_bounds__(256) void k2_vlad(const float* __restrict__ x)
{
    __shared__ float xs[128][36];   // x^T chunk [d][n]
    __shared__ float as[32][72];    // assign chunk [n][k]

    const int tid  = threadIdx.x;
    const int lane = tid & 31;
    const int w    = tid >> 5;
    const int la   = lane >> 2;
    const int lb   = lane & 3;
    const int b    = blockIdx.y;
    const int d0   = blockIdx.x * 128;
    const int s    = blockIdx.z;
    const int nbase = s * (Nn / NSPLIT);    // 1024 rows per split

    // x loader: thread -> n row (tid&31), d segment (tid>>5)*16
    const int nr = tid & 31;
    const int dc = (tid >> 5) * 16;
    // assign loader
    const int ar = tid >> 3;              // 0..31
    const int akc = (tid & 7) * 8;        // 0..56

    const float* xg = x + ((size_t)b * Nn + nbase) * Dd + d0;
    const float* ag = g_assign + ((size_t)b * Nn + nbase) * Kk;

    float acc[8][4];
#pragma unroll
    for (int j = 0; j < 8; j++)
#pragma unroll
        for (int q = 0; q < 4; q++) acc[j][q] = 0.0f;

    float4 px[4];
    float4 pa[2];
#pragma unroll
    for (int q = 0; q < 4; q++)
        px[q] = *(const float4*)&xg[(size_t)nr * Dd + dc + q * 4];
#pragma unroll
    for (int q = 0; q < 2; q++)
        pa[q] = *(const float4*)&ag[(size_t)ar * Kk + akc + q * 4];

    for (int c = 0; c < 32; c++) {
        // store x transposed (scalar, conflict-free: bank = 4d + n)
#pragma unroll
        for (int q = 0; q < 4; q++) {
            xs[dc + q * 4 + 0][nr] = px[q].x;
            xs[dc + q * 4 + 1][nr] = px[q].y;
            xs[dc + q * 4 + 2][nr] = px[q].z;
            xs[dc + q * 4 + 3][nr] = px[q].w;
        }
#pragma unroll
        for (int q = 0; q < 2; q++)
            *(float4*)&as[ar][akc + q * 4] = pa[q];
        __syncthreads();

        if (c < 31) {
            int n0 = (c + 1) * 32;
#pragma unroll
            for (int q = 0; q < 4; q++)
                px[q] = *(const float4*)&xg[(size_t)(n0 + nr) * Dd + dc + q * 4];
#pragma unroll
            for (int q = 0; q < 2; q++)
                pa[q] = *(const float4*)&ag[(size_t)(n0 + ar) * Kk + akc + q * 4];
        }

        const int wr = w * 16 + la;
#pragma unroll
        for (int kk = 0; kk < 4; kk++) {
            uint32_t a0 = __float_as_uint(xs[wr][kk * 8 + lb]);
            uint32_t a1 = __float_as_uint(xs[wr + 8][kk * 8 + lb]);
            uint32_t a2 = __float_as_uint(xs[wr][kk * 8 + 4 + lb]);
            uint32_t a3 = __float_as_uint(xs[wr + 8][kk * 8 + 4 + lb]);
#pragma unroll
            for (int j = 0; j < 8; j++) {
                uint32_t b0 = __float_as_uint(as[kk * 8 + lb][j * 8 + la]);
                uint32_t b1 = __float_as_uint(as[kk * 8 + 4 + lb][j * 8 + la]);
                mma8(acc[j], a0, a1, a2, a3, b0, b1);
            }
        }
        __syncthreads();
    }

    // epilogue: scatter to g_vpart[s][b][k][d]
    float* vp = g_vpart + ((size_t)s * Bb + b) * Kk * Dd;
    const int gdA = d0 + w * 16 + la;
    const int gdB = gdA + 8;
#pragma unroll
    for (int j = 0; j < 8; j++)
#pragma unroll
        for (int e = 0; e < 2; e++) {
            int col = j * 8 + lb * 2 + e;
            vp[(size_t)col * Dd + gdA] = acc[j][e];
            vp[(size_t)col * Dd + gdB] = acc[j][2 + e];
        }
}

// ---------------------------------------------------------------------------
// k3: sum partials, subtract a_sum*clusters2, intra-normalize over D,
//     accumulate global sumsq.
// ---------------------------------------------------------------------------
__global__ __launch_bounds__(128) void k3_colnorm(const float* __restrict__ c2,
                                                  float* __restrict__ out)
{
    const int bk = blockIdx.x;          // b*64 + k
    const int b = bk >> 6;
    const int k = bk & 63;
    const int tid = threadIdx.x;
    const size_t SP = (size_t)Bb * Kk * Dd;   // split plane stride

    const float a = g_asum[bk];
    const float* vr = g_vpart + (size_t)bk * Dd;

    float v[4];
    float ss = 0.0f;
#pragma unroll
    for (int p = 0; p < 4; p++) {
        int d = tid + p * 128;
        float t = vr[d] + vr[d + SP] + vr[d + 2 * SP] + vr[d + 3 * SP]
                - a * c2[(size_t)d * Kk + k];
        v[p] = t;
        ss += t * t;
    }
#pragma unroll
    for (int o = 16; o; o >>= 1) ss += __shfl_xor_sync(0xffffffffu, ss, o);

    __shared__ float sred[4];
    if ((tid & 31) == 0) sred[tid >> 5] = ss;
    __syncthreads();
    float tot = sred[0] + sred[1] + sred[2] + sred[3];
    float inv = 1.0f / fmaxf(sqrtf(tot), 1e-12f);
    if (tid == 0) atomicAdd(&g_gnormsq[b], tot * inv * inv);

    float* ob = out + (size_t)b * (Dd * Kk);
#pragma unroll
    for (int p = 0; p < 4; p++) {
        int d = tid + p * 128;
        ob[(size_t)d * Kk + k] = v[p] * inv;
    }
}

// ---------------------------------------------------------------------------
__global__ void k4_scale(float* __restrict__ out)
{
    int idx = blockIdx.x * 256 + threadIdx.x;
    int b = idx >> 15;
    out[idx] *= 1.0f / fmaxf(sqrtf(g_gnormsq[b]), 1e-12f);
}

// ---------------------------------------------------------------------------
extern "C" void kernel_launch(void* const* d_in, const int* in_sizes, int n_in,
                              void* d_out, int out_size)
{
    const float* x        = (const float*)d_in[0];
    const float* clusters = (const float*)d_in[1];
    const float* c2       = (const float*)d_in[2];
    const float* bnw      = (const float*)d_in[3];
    const float* bnb      = (const float*)d_in[4];
    const float* rm       = (const float*)d_in[5];
    const float* rv       = (const float*)d_in[6];
    float* out = (float*)d_out;

    k0_init<<<8, 256>>>();
    k1_logits_softmax<<<(Bb * Nn) / 128, 256>>>(x, clusters, bnw, bnb, rm, rv);
    dim3 g2(Dd / 128, Bb, NSPLIT);
    k2_vlad<<<g2, 256>>>(x);
    k3_colnorm<<<Bb * Kk, 128>>>(c2, out);
    k4_scale<<<(Bb * Dd * Kk) / 256, 256>>>(out);
}

// round 8
// speedup vs baseline: 1.3750x; 1.3750x over previous
#include <cuda_runtime.h>
#include <math.h>
#include <stdint.h>

// B=32, N=4096, D=512, K=64
#define Bb 32
#define Nn 4096
#define Dd 512
#define Kk 64
#define NSPLIT 2

__device__ float g_assign[(size_t)Bb * Nn * Kk];            // softmax assignments [b,n,k]
__device__ float g_vpart[(size_t)NSPLIT * Bb * Kk * Dd];    // vlad partials [s,b,k,d]
__device__ float g_asum[Bb * Kk];
__device__ float g_gnormsq[Bb];

// ---- tf32 helpers ----------------------------------------------------------
__device__ __forceinline__ uint32_t tf32b(float f) {
    uint32_t u; asm("cvt.rna.tf32.f32 %0, %1;" : "=r"(u) : "f"(f)); return u;
}
__device__ __forceinline__ float tf32f(float f) { return __uint_as_float(tf32b(f)); }

__device__ __forceinline__ void mma8(float* c, uint32_t a0, uint32_t a1,
                                     uint32_t a2, uint32_t a3,
                                     uint32_t b0, uint32_t b1) {
    asm volatile(
        "mma.sync.aligned.m16n8k8.row.col.f32.tf32.tf32.f32 "
        "{%0,%1,%2,%3},{%4,%5,%6,%7},{%8,%9},{%0,%1,%2,%3};\n"
        : "+f"(c[0]), "+f"(c[1]), "+f"(c[2]), "+f"(c[3])
        : "r"(a0), "r"(a1), "r"(a2), "r"(a3), "r"(b0), "r"(b1));
}

// ---------------------------------------------------------------------------
__global__ void k0_init() {
    int i = blockIdx.x * 256 + threadIdx.x;
    if (i < Bb * Kk) g_asum[i] = 0.0f;
    if (i < Bb)      g_gnormsq[i] = 0.0f;
}

// ---------------------------------------------------------------------------
// k1: logits = x @ clusters (131072x512 @ 512x64) via tf32 MMA, fused
// BN(eval) + softmax + assignment store + a_sum atomic.  (identical to R6)
// ---------------------------------------------------------------------------
__global__ __launch_bounds__(256) void k1_logits_softmax(
    const float* __restrict__ x,
    const float* __restrict__ clusters,
    const float* __restrict__ bnw,
    const float* __restrict__ bnb,
    const float* __restrict__ rm,
    const float* __restrict__ rv)
{
    __shared__ float xs[128][36];   // [row][k], bank = 4*row+k (conflict-free)
    __shared__ float cs[32][72];    // [k][n],  bank = 8*k+n   (conflict-free)
    __shared__ float scf[64], shf[64];
    __shared__ float red[8 * 64];

    const int tid  = threadIdx.x;
    const int lane = tid & 31;
    const int w    = tid >> 5;
    const int la   = lane >> 2;     // 0..7
    const int lb   = lane & 3;      // 0..3
    const int row0 = blockIdx.x * 128;

    const int xr = tid >> 1;              // 0..127
    const int xc = (tid & 1) * 16;        // 0 or 16
    const int cr = tid >> 3;              // 0..31
    const int cc = (tid & 7) * 8;         // 0..56

    const float* xg = x + (size_t)row0 * Dd;

    float acc[8][4];
#pragma unroll
    for (int j = 0; j < 8; j++)
#pragma unroll
        for (int q = 0; q < 4; q++) acc[j][q] = 0.0f;

    float4 px[4];
    float4 pc[2];
#pragma unroll
    for (int q = 0; q < 4; q++)
        px[q] = *(const float4*)&xg[(size_t)xr * Dd + xc + q * 4];
#pragma unroll
    for (int q = 0; q < 2; q++)
        pc[q] = *(const float4*)&clusters[(size_t)cr * Kk + cc + q * 4];

    for (int c = 0; c < 16; c++) {
#pragma unroll
        for (int q = 0; q < 4; q++) {
            float4 t = make_float4(tf32f(px[q].x), tf32f(px[q].y),
                                   tf32f(px[q].z), tf32f(px[q].w));
            *(float4*)&xs[xr][xc + q * 4] = t;
        }
#pragma unroll
        for (int q = 0; q < 2; q++) {
            float4 t = make_float4(tf32f(pc[q].x), tf32f(pc[q].y),
                                   tf32f(pc[q].z), tf32f(pc[q].w));
            *(float4*)&cs[cr][cc + q * 4] = t;
        }
        __syncthreads();

        if (c < 15) {
            int d0 = (c + 1) * 32;
#pragma unroll
            for (int q = 0; q < 4; q++)
                px[q] = *(const float4*)&xg[(size_t)xr * Dd + d0 + xc + q * 4];
#pragma unroll
            for (int q = 0; q < 2; q++)
                pc[q] = *(const float4*)&clusters[(size_t)(d0 + cr) * Kk + cc + q * 4];
        }

        const int wr = w * 16 + la;
#pragma unroll
        for (int kk = 0; kk < 4; kk++) {
            uint32_t a0 = __float_as_uint(xs[wr][kk * 8 + lb]);
            uint32_t a1 = __float_as_uint(xs[wr + 8][kk * 8 + lb]);
            uint32_t a2 = __float_as_uint(xs[wr][kk * 8 + 4 + lb]);
            uint32_t a3 = __float_as_uint(xs[wr + 8][kk * 8 + 4 + lb]);
#pragma unroll
            for (int j = 0; j < 8; j++) {
                uint32_t b0 = __float_as_uint(cs[kk * 8 + lb][j * 8 + la]);
                uint32_t b1 = __float_as_uint(cs[kk * 8 + 4 + lb][j * 8 + la]);
                mma8(acc[j], a0, a1, a2, a3, b0, b1);
            }
        }
        __syncthreads();
    }

    // ---- epilogue: BN + softmax + store + a_sum ----
    if (tid < 64) {
        float istd = rsqrtf(rv[tid] + 1e-5f);
        float s = bnw[tid] * istd;
        scf[tid] = s;
        shf[tid] = bnb[tid] - rm[tid] * s;
    }
    __syncthreads();

    float vA[8][2], vB[8][2];
#pragma unroll
    for (int j = 0; j < 8; j++)
#pragma unroll
        for (int e = 0; e < 2; e++) {
            int col = j * 8 + lb * 2 + e;
            float s = scf[col], h = shf[col];
            vA[j][e] = acc[j][e]     * s + h;
            vB[j][e] = acc[j][2 + e] * s + h;
        }

    float mA = -1e30f, mB = -1e30f;
#pragma unroll
    for (int j = 0; j < 8; j++)
#pragma unroll
        for (int e = 0; e < 2; e++) { mA = fmaxf(mA, vA[j][e]); mB = fmaxf(mB, vB[j][e]); }
    mA = fmaxf(mA, __shfl_xor_sync(0xffffffffu, mA, 1));
    mA = fmaxf(mA, __shfl_xor_sync(0xffffffffu, mA, 2));
    mB = fmaxf(mB, __shfl_xor_sync(0xffffffffu, mB, 1));
    mB = fmaxf(mB, __shfl_xor_sync(0xffffffffu, mB, 2));
    float sA = 0.0f, sB = 0.0f;
#pragma unroll
    for (int j = 0; j < 8; j++)
#pragma unroll
        for (int e = 0; e < 2; e++) {
            vA[j][e] = __expf(vA[j][e] - mA); sA += vA[j][e];
            vB[j][e] = __expf(vB[j][e] - mB); sB += vB[j][e];
        }
    sA += __shfl_xor_sync(0xffffffffu, sA, 1);
    sA += __shfl_xor_sync(0xffffffffu, sA, 2);
    sB += __shfl_xor_sync(0xffffffffu, sB, 1);
    sB += __shfl_xor_sync(0xffffffffu, sB, 2);
    float invA = 1.0f / sA, invB = 1.0f / sB;

    float csum[8][2];
    const int grA = row0 + w * 16 + la;
    const int grB = grA + 8;
    float* ag = g_assign;
#pragma unroll
    for (int j = 0; j < 8; j++) {
#pragma unroll
        for (int e = 0; e < 2; e++) {
            vA[j][e] *= invA;
            vB[j][e] *= invB;
            csum[j][e] = vA[j][e] + vB[j][e];
        }
        *(float2*)&ag[(size_t)grA * Kk + j * 8 + lb * 2] = make_float2(vA[j][0], vA[j][1]);
        *(float2*)&ag[(size_t)grB * Kk + j * 8 + lb * 2] = make_float2(vB[j][0], vB[j][1]);
    }

#pragma unroll
    for (int j = 0; j < 8; j++)
#pragma unroll
        for (int e = 0; e < 2; e++) {
            csum[j][e] += __shfl_xor_sync(0xffffffffu, csum[j][e], 4);
            csum[j][e] += __shfl_xor_sync(0xffffffffu, csum[j][e], 8);
            csum[j][e] += __shfl_xor_sync(0xffffffffu, csum[j][e], 16);
        }
    if (la == 0) {
#pragma unroll
        for (int j = 0; j < 8; j++)
#pragma unroll
            for (int e = 0; e < 2; e++)
                red[w * 64 + j * 8 + lb * 2 + e] = csum[j][e];
    }
    __syncthreads();
    if (tid < 64) {
        float s = 0.0f;
#pragma unroll
        for (int q = 0; q < 8; q++) s += red[q * 64 + tid];
        atomicAdd(&g_asum[(row0 >> 12) * Kk + tid], s);
    }
}

// ---------------------------------------------------------------------------
// k2: vlad partials via tf32 MMA — R6 shape (128 thr, 4 warps, 64d x 64k,
// n-chunk 32), ONE change: N split in 2 across blockIdx.z, 64 chunks each,
// partials to g_vpart[s]. Grid (8, 32, 2) = 512 blocks.
// ---------------------------------------------------------------------------
__global__ __launch_bounds__(128) void k2_vlad(const float* __restrict__ x)
{
    __shared__ float xs[64][36];    // x^T chunk [d][n], bank = d*4+n (perfect)
    __shared__ float as[32][72];    // assign chunk [n][k], bank = n*8+k (perfect)

    const int tid  = threadIdx.x;
    const int lane = tid & 31;
    const int w    = tid >> 5;
    const int la   = lane >> 2;
    const int lb   = lane & 3;
    const int b    = blockIdx.y;
    const int d0   = blockIdx.x * 64;
    const int s    = blockIdx.z;
    const int nbase = s * (Nn / NSPLIT);   // 2048 rows per split

    const int nr = tid & 31;
    const int dc = (tid >> 5) * 16;
    const int ar = tid >> 2;
    const int akc = (tid & 3) * 16;

    const float* xg = x + ((size_t)b * Nn + nbase) * Dd + d0;
    const float* ag = g_assign + ((size_t)b * Nn + nbase) * Kk;

    float acc[8][4];
#pragma unroll
    for (int j = 0; j < 8; j++)
#pragma unroll
        for (int q = 0; q < 4; q++) acc[j][q] = 0.0f;

    float4 px[4], pa[4];
#pragma unroll
    for (int q = 0; q < 4; q++) {
        px[q] = *(const float4*)&xg[(size_t)nr * Dd + dc + q * 4];
        pa[q] = *(const float4*)&ag[(size_t)ar * Kk + akc + q * 4];
    }

    for (int c = 0; c < Nn / NSPLIT / 32; c++) {
#pragma unroll
        for (int q = 0; q < 4; q++) {
            xs[dc + q * 4 + 0][nr] = tf32f(px[q].x);
            xs[dc + q * 4 + 1][nr] = tf32f(px[q].y);
            xs[dc + q * 4 + 2][nr] = tf32f(px[q].z);
            xs[dc + q * 4 + 3][nr] = tf32f(px[q].w);
            float4 t = make_float4(tf32f(pa[q].x), tf32f(pa[q].y),
                                   tf32f(pa[q].z), tf32f(pa[q].w));
            *(float4*)&as[ar][akc + q * 4] = t;
        }
        __syncthreads();

        if (c < Nn / NSPLIT / 32 - 1) {
            int n0 = (c + 1) * 32;
#pragma unroll
            for (int q = 0; q < 4; q++) {
                px[q] = *(const float4*)&xg[(size_t)(n0 + nr) * Dd + dc + q * 4];
                pa[q] = *(const float4*)&ag[(size_t)(n0 + ar) * Kk + akc + q * 4];
            }
        }

        const int wr = w * 16 + la;
#pragma unroll
        for (int kk = 0; kk < 4; kk++) {
            uint32_t a0 = __float_as_uint(xs[wr][kk * 8 + lb]);
            uint32_t a1 = __float_as_uint(xs[wr + 8][kk * 8 + lb]);
            uint32_t a2 = __float_as_uint(xs[wr][kk * 8 + 4 + lb]);
            uint32_t a3 = __float_as_uint(xs[wr + 8][kk * 8 + 4 + lb]);
#pragma unroll
            for (int j = 0; j < 8; j++) {
                uint32_t b0 = __float_as_uint(as[kk * 8 + lb][j * 8 + la]);
                uint32_t b1 = __float_as_uint(as[kk * 8 + 4 + lb][j * 8 + la]);
                mma8(acc[j], a0, a1, a2, a3, b0, b1);
            }
        }
        __syncthreads();
    }

    // epilogue: scatter to g_vpart[s][b][k][d]
    float* vp = g_vpart + ((size_t)s * Bb + b) * Kk * Dd;
    const int gdA = d0 + w * 16 + la;
    const int gdB = gdA + 8;
#pragma unroll
    for (int j = 0; j < 8; j++)
#pragma unroll
        for (int e = 0; e < 2; e++) {
            int col = j * 8 + lb * 2 + e;
            vp[(size_t)col * Dd + gdA] = acc[j][e];
            vp[(size_t)col * Dd + gdB] = acc[j][2 + e];
        }
}

// ---------------------------------------------------------------------------
// k3: sum partials, subtract a_sum*clusters2, intra-normalize over D,
//     accumulate global sumsq.
// ---------------------------------------------------------------------------
__global__ __launch_bounds__(128) void k3_colnorm(const float* __restrict__ c2,
                                                  float* __restrict__ out)
{
    const int bk = blockIdx.x;          // b*64 + k
    const int b = bk >> 6;
    const int k = bk & 63;
    const int tid = threadIdx.x;
    const size_t SP = (size_t)Bb * Kk * Dd;

    const float a = g_asum[bk];
    const float* vr = g_vpart + (size_t)bk * Dd;

    float v[4];
    float ss = 0.0f;
#pragma unroll
    for (int p = 0; p < 4; p++) {
        int d = tid + p * 128;
        float t = vr[d] + vr[d + SP] - a * c2[(size_t)d * Kk + k];
        v[p] = t;
        ss += t * t;
    }
#pragma unroll
    for (int o = 16; o; o >>= 1) ss += __shfl_xor_sync(0xffffffffu, ss, o);

    __shared__ float sred[4];
    if ((tid & 31) == 0) sred[tid >> 5] = ss;
    __syncthreads();
    float tot = sred[0] + sred[1] + sred[2] + sred[3];
    float inv = 1.0f / fmaxf(sqrtf(tot), 1e-12f);
    if (tid == 0) atomicAdd(&g_gnormsq[b], tot * inv * inv);

    float* ob = out + (size_t)b * (Dd * Kk);
#pragma unroll
    for (int p = 0; p < 4; p++) {
        int d = tid + p * 128;
        ob[(size_t)d * Kk + k] = v[p] * inv;
    }
}

// ---------------------------------------------------------------------------
__global__ void k4_scale(float* __restrict__ out)
{
    int idx = blockIdx.x * 256 + threadIdx.x;
    int b = idx >> 15;
    out[idx] *= 1.0f / fmaxf(sqrtf(g_gnormsq[b]), 1e-12f);
}

// ---------------------------------------------------------------------------
extern "C" void kernel_launch(void* const* d_in, const int* in_sizes, int n_in,
                              void* d_out, int out_size)
{
    const float* x        = (const float*)d_in[0];
    const float* clusters = (const float*)d_in[1];
    const float* c2       = (const float*)d_in[2];
    const float* bnw      = (const float*)d_in[3];
    const float* bnb      = (const float*)d_in[4];
    const float* rm       = (const float*)d_in[5];
    const float* rv       = (const float*)d_in[6];
    float* out = (float*)d_out;

    k0_init<<<8, 256>>>();
    k1_logits_softmax<<<(Bb * Nn) / 128, 256>>>(x, clusters, bnw, bnb, rm, rv);
    dim3 g2(Dd / 64, Bb, NSPLIT);
    k2_vlad<<<g2, 128>>>(x);
    k3_colnorm<<<Bb * Kk, 128>>>(c2, out);
    k4_scale<<<(Bb * Dd * Kk) / 256, 256>>>(out);
}

// round 10
// speedup vs baseline: 1.4965x; 1.0884x over previous
#include <cuda_runtime.h>
#include <cuda_fp16.h>
#include <math.h>
#include <stdint.h>

// B=32, N=4096, D=512, K=64
#define Bb 32
#define Nn 4096
#define Dd 512
#define Kk 64
#define NSPLIT 2

__device__ float g_assign[(size_t)Bb * Nn * Kk];            // softmax assignments [b,n,k]
__device__ float g_vpart[(size_t)NSPLIT * Bb * Kk * Dd];    // vlad partials [s,b,k,d]
__device__ float g_asum[Bb * Kk];
__device__ float g_gnormsq[Bb];

// pack two floats -> half2 (lo, hi) as uint32
__device__ __forceinline__ uint32_t h2pack(float lo, float hi) {
    __half2 h = __floats2half2_rn(lo, hi);
    return *(uint32_t*)&h;
}

// fp16 HMMA m16n8k16, fp32 accumulate
__device__ __forceinline__ void mma16(float* c, uint32_t a0, uint32_t a1,
                                      uint32_t a2, uint32_t a3,
                                      uint32_t b0, uint32_t b1) {
    asm volatile(
        "mma.sync.aligned.m16n8k16.row.col.f32.f16.f16.f32 "
        "{%0,%1,%2,%3},{%4,%5,%6,%7},{%8,%9},{%0,%1,%2,%3};\n"
        : "+f"(c[0]), "+f"(c[1]), "+f"(c[2]), "+f"(c[3])
        : "r"(a0), "r"(a1), "r"(a2), "r"(a3), "r"(b0), "r"(b1));
}

// ---------------------------------------------------------------------------
__global__ void k0_init() {
    int i = blockIdx.x * 256 + threadIdx.x;
    if (i < Bb * Kk) g_asum[i] = 0.0f;
    if (i < Bb)      g_gnormsq[i] = 0.0f;
}

// ---------------------------------------------------------------------------
// k1: logits = x @ clusters (131072x512 @ 512x64) via fp16 MMA m16n8k16,
// fused BN(eval) + softmax + assignment store + a_sum atomic.
// Block: 256 thr (8 warps), tile 128 rows x 64 cols, K chunk 32 (2 ksteps).
// smem granules: xs[row][g] packs x(d=2g,2g+1); cs[n][g] packs clusters(d=2g,2g+1).
// ---------------------------------------------------------------------------
__global__ __launch_bounds__(256) void k1_logits_softmax(
    const float* __restrict__ x,
    const float* __restrict__ clusters,
    const float* __restrict__ bnw,
    const float* __restrict__ bnb,
    const float* __restrict__ rm,
    const float* __restrict__ rv)
{
    __shared__ uint32_t xs[128][20];   // frag-load bank = 20*la+lb : conflict-free
    __shared__ uint32_t cs[64][20];
    __shared__ float scf[64], shf[64];
    __shared__ float red[8 * 64];

    const int tid  = threadIdx.x;
    const int lane = tid & 31;
    const int w    = tid >> 5;
    const int la   = lane >> 2;     // 0..7
    const int lb   = lane & 3;      // 0..3
    const int row0 = blockIdx.x * 128;

    // x loader: row = tid>>1, 16 floats at (tid&1)*16
    const int xr  = tid >> 1;
    const int xc4 = (tid & 1) * 16;
    // clusters loader: n = tid&63, 4 granules at (tid>>6)*4
    const int cn = tid & 63;
    const int ck = (tid >> 6) * 4;

    const float* xg = x + (size_t)row0 * Dd;

    float acc[8][4];
#pragma unroll
    for (int j = 0; j < 8; j++)
#pragma unroll
        for (int q = 0; q < 4; q++) acc[j][q] = 0.0f;

    float4 px[4];
    float pcl[8];
#pragma unroll
    for (int q = 0; q < 4; q++)
        px[q] = *(const float4*)&xg[(size_t)xr * Dd + xc4 + q * 4];
#pragma unroll
    for (int g = 0; g < 4; g++) {
        pcl[2 * g]     = clusters[(size_t)(2 * (ck + g))     * Kk + cn];
        pcl[2 * g + 1] = clusters[(size_t)(2 * (ck + g) + 1) * Kk + cn];
    }

    for (int c = 0; c < 16; c++) {
#pragma unroll
        for (int q = 0; q < 4; q++) {
            xs[xr][(xc4 >> 1) + 2 * q]     = h2pack(px[q].x, px[q].y);
            xs[xr][(xc4 >> 1) + 2 * q + 1] = h2pack(px[q].z, px[q].w);
        }
#pragma unroll
        for (int g = 0; g < 4; g++)
            cs[cn][ck + g] = h2pack(pcl[2 * g], pcl[2 * g + 1]);
        __syncthreads();

        if (c < 15) {
            int d0 = (c + 1) * 32;
#pragma unroll
            for (int q = 0; q < 4; q++)
                px[q] = *(const float4*)&xg[(size_t)xr * Dd + d0 + xc4 + q * 4];
#pragma unroll
            for (int g = 0; g < 4; g++) {
                pcl[2 * g]     = clusters[(size_t)(d0 + 2 * (ck + g))     * Kk + cn];
                pcl[2 * g + 1] = clusters[(size_t)(d0 + 2 * (ck + g) + 1) * Kk + cn];
            }
        }

        const int wr = w * 16 + la;
#pragma unroll
        for (int s = 0; s < 2; s++) {
            uint32_t a0 = xs[wr][s * 8 + lb];
            uint32_t a1 = xs[wr + 8][s * 8 + lb];
            uint32_t a2 = xs[wr][s * 8 + 4 + lb];
            uint32_t a3 = xs[wr + 8][s * 8 + 4 + lb];
#pragma unroll
            for (int j = 0; j < 8; j++) {
                uint32_t b0 = cs[j * 8 + la][s * 8 + lb];
                uint32_t b1 = cs[j * 8 + la][s * 8 + 4 + lb];
                mma16(acc[j], a0, a1, a2, a3, b0, b1);
            }
        }
        __syncthreads();
    }

    // ---- epilogue: BN + softmax + store + a_sum ----
    if (tid < 64) {
        float istd = rsqrtf(rv[tid] + 1e-5f);
        float s = bnw[tid] * istd;
        scf[tid] = s;
        shf[tid] = bnb[tid] - rm[tid] * s;
    }
    __syncthreads();

    float vA[8][2], vB[8][2];
#pragma unroll
    for (int j = 0; j < 8; j++)
#pragma unroll
        for (int e = 0; e < 2; e++) {
            int col = j * 8 + lb * 2 + e;
            float s = scf[col], h = shf[col];
            vA[j][e] = acc[j][e]     * s + h;
            vB[j][e] = acc[j][2 + e] * s + h;
        }

    float mA = -1e30f, mB = -1e30f;
#pragma unroll
    for (int j = 0; j < 8; j++)
#pragma unroll
        for (int e = 0; e < 2; e++) { mA = fmaxf(mA, vA[j][e]); mB = fmaxf(mB, vB[j][e]); }
    mA = fmaxf(mA, __shfl_xor_sync(0xffffffffu, mA, 1));
    mA = fmaxf(mA, __shfl_xor_sync(0xffffffffu, mA, 2));
    mB = fmaxf(mB, __shfl_xor_sync(0xffffffffu, mB, 1));
    mB = fmaxf(mB, __shfl_xor_sync(0xffffffffu, mB, 2));
    float sA = 0.0f, sB = 0.0f;
#pragma unroll
    for (int j = 0; j < 8; j++)
#pragma unroll
        for (int e = 0; e < 2; e++) {
            vA[j][e] = __expf(vA[j][e] - mA); sA += vA[j][e];
            vB[j][e] = __expf(vB[j][e] - mB); sB += vB[j][e];
        }
    sA += __shfl_xor_sync(0xffffffffu, sA, 1);
    sA += __shfl_xor_sync(0xffffffffu, sA, 2);
    sB += __shfl_xor_sync(0xffffffffu, sB, 1);
    sB += __shfl_xor_sync(0xffffffffu, sB, 2);
    float invA = 1.0f / sA, invB = 1.0f / sB;

    float csum[8][2];
    const int grA = row0 + w * 16 + la;
    const int grB = grA + 8;
    float* ag = g_assign;
#pragma unroll
    for (int j = 0; j < 8; j++) {
#pragma unroll
        for (int e = 0; e < 2; e++) {
            vA[j][e] *= invA;
            vB[j][e] *= invB;
            csum[j][e] = vA[j][e] + vB[j][e];
        }
        *(float2*)&ag[(size_t)grA * Kk + j * 8 + lb * 2] = make_float2(vA[j][0], vA[j][1]);
        *(float2*)&ag[(size_t)grB * Kk + j * 8 + lb * 2] = make_float2(vB[j][0], vB[j][1]);
    }

#pragma unroll
    for (int j = 0; j < 8; j++)
#pragma unroll
        for (int e = 0; e < 2; e++) {
            csum[j][e] += __shfl_xor_sync(0xffffffffu, csum[j][e], 4);
            csum[j][e] += __shfl_xor_sync(0xffffffffu, csum[j][e], 8);
            csum[j][e] += __shfl_xor_sync(0xffffffffu, csum[j][e], 16);
        }
    if (la == 0) {
#pragma unroll
        for (int j = 0; j < 8; j++)
#pragma unroll
            for (int e = 0; e < 2; e++)
                red[w * 64 + j * 8 + lb * 2 + e] = csum[j][e];
    }
    __syncthreads();
    if (tid < 64) {
        float s = 0.0f;
#pragma unroll
        for (int q = 0; q < 8; q++) s += red[q * 64 + tid];
        atomicAdd(&g_asum[(row0 >> 12) * Kk + tid], s);
    }
}

// ---------------------------------------------------------------------------
// k2: vlad partials via fp16 MMA. A = x^T [d][n-pairs], B = assign^T [k][n-pairs].
// Block: 128 thr (4 warps), tile d=64 x k=64, n-chunk 32 (2 ksteps),
// NSPLIT=2 across blockIdx.z. Grid (8, 32, 2).
// ---------------------------------------------------------------------------
__global__ __launch_bounds__(128) void k2_vlad(const float* __restrict__ x)
{
    __shared__ uint32_t xs[64][20];   // [d][n-granule]
    __shared__ uint32_t as[64][20];   // [k][n-granule]

    const int tid  = threadIdx.x;
    const int lane = tid & 31;
    const int w    = tid >> 5;
    const int la   = lane >> 2;
    const int lb   = lane & 3;
    const int b    = blockIdx.y;
    const int d0   = blockIdx.x * 64;
    const int s    = blockIdx.z;
    const int nbase = s * (Nn / NSPLIT);

    // loaders: thread -> n-pair nn = tid&15, 8-wide segment (tid>>4)*8
    const int nn = tid & 15;
    const int sg = (tid >> 4) * 8;

    const float* xg = x + ((size_t)b * Nn + nbase) * Dd + d0;
    const float* ag = g_assign + ((size_t)b * Nn + nbase) * Kk;

    float acc[8][4];
#pragma unroll
    for (int j = 0; j < 8; j++)
#pragma unroll
        for (int q = 0; q < 4; q++) acc[j][q] = 0.0f;

    float4 pxl[2], pxh[2], pal[2], pah[2];
#pragma unroll
    for (int q = 0; q < 2; q++) {
        pxl[q] = *(const float4*)&xg[(size_t)(2 * nn)     * Dd + sg + q * 4];
        pxh[q] = *(const float4*)&xg[(size_t)(2 * nn + 1) * Dd + sg + q * 4];
        pal[q] = *(const float4*)&ag[(size_t)(2 * nn)     * Kk + sg + q * 4];
        pah[q] = *(const float4*)&ag[(size_t)(2 * nn + 1) * Kk + sg + q * 4];
    }

    for (int c = 0; c < Nn / NSPLIT / 32; c++) {
        // transpose-pack into granules: xs[d][nn] = (x[2nn][d], x[2nn+1][d])
        {
            float xl[8] = { pxl[0].x, pxl[0].y, pxl[0].z, pxl[0].w,
                            pxl[1].x, pxl[1].y, pxl[1].z, pxl[1].w };
            float xh[8] = { pxh[0].x, pxh[0].y, pxh[0].z, pxh[0].w,
                            pxh[1].x, pxh[1].y, pxh[1].z, pxh[1].w };
            float al[8] = { pal[0].x, pal[0].y, pal[0].z, pal[0].w,
                            pal[1].x, pal[1].y, pal[1].z, pal[1].w };
            float ah[8] = { pah[0].x, pah[0].y, pah[0].z, pah[0].w,
                            pah[1].x, pah[1].y, pah[1].z, pah[1].w };
#pragma unroll
            for (int e = 0; e < 8; e++) {
                xs[sg + e][nn] = h2pack(xl[e], xh[e]);
                as[sg + e][nn] = h2pack(al[e], ah[e]);
            }
        }
        __syncthreads();

        if (c < Nn / NSPLIT / 32 - 1) {
            int n0 = (c + 1) * 32;
#pragma unroll
            for (int q = 0; q < 2; q++) {
                pxl[q] = *(const float4*)&xg[(size_t)(n0 + 2 * nn)     * Dd + sg + q * 4];
                pxh[q] = *(const float4*)&xg[(size_t)(n0 + 2 * nn + 1) * Dd + sg + q * 4];
                pal[q] = *(const float4*)&ag[(size_t)(n0 + 2 * nn)     * Kk + sg + q * 4];
                pah[q] = *(const float4*)&ag[(size_t)(n0 + 2 * nn + 1) * Kk + sg + q * 4];
            }
        }

        const int wr = w * 16 + la;
#pragma unroll
        for (int ss = 0; ss < 2; ss++) {
            uint32_t a0 = xs[wr][ss * 8 + lb];
            uint32_t a1 = xs[wr + 8][ss * 8 + lb];
            uint32_t a2 = xs[wr][ss * 8 + 4 + lb];
            uint32_t a3 = xs[wr + 8][ss * 8 + 4 + lb];
#pragma unroll
            for (int j = 0; j < 8; j++) {
                uint32_t b0 = as[j * 8 + la][ss * 8 + lb];
                uint32_t b1 = as[j * 8 + la][ss * 8 + 4 + lb];
                mma16(acc[j], a0, a1, a2, a3, b0, b1);
            }
        }
        __syncthreads();
    }

    // epilogue: scatter to g_vpart[s][b][k][d]
    float* vp = g_vpart + ((size_t)s * Bb + b) * Kk * Dd;
    const int gdA = d0 + w * 16 + la;
    const int gdB = gdA + 8;
#pragma unroll
    for (int j = 0; j < 8; j++)
#pragma unroll
        for (int e = 0; e < 2; e++) {
            int col = j * 8 + lb * 2 + e;
            vp[(size_t)col * Dd + gdA] = acc[j][e];
            vp[(size_t)col * Dd + gdB] = acc[j][2 + e];
        }
}

// ---------------------------------------------------------------------------
// k3: sum partials, subtract a_sum*clusters2, intra-normalize over D,
//     accumulate global sumsq.
// ---------------------------------------------------------------------------
__global__ __launch_bounds__(128) void k3_colnorm(const float* __restrict__ c2,
                                                  float* __restrict__ out)
{
    const int bk = blockIdx.x;
    const int b = bk >> 6;
    const int k = bk & 63;
    const int tid = threadIdx.x;
    const size_t SP = (size_t)Bb * Kk * Dd;

    const float a = g_asum[bk];
    const float* vr = g_vpart + (size_t)bk * Dd;

    float v[4];
    float ss = 0.0f;
#pragma unroll
    for (int p = 0; p < 4; p++) {
        int d = tid + p * 128;
        float t = vr[d] + vr[d + SP] - a * c2[(size_t)d * Kk + k];
        v[p] = t;
        ss += t * t;
    }
#pragma unroll
    for (int o = 16; o; o >>= 1) ss += __shfl_xor_sync(0xffffffffu, ss, o);

    __shared__ float sred[4];
    if ((tid & 31) == 0) sred[tid >> 5] = ss;
    __syncthreads();
    float tot = sred[0] + sred[1] + sred[2] + sred[3];
    float inv = 1.0f / fmaxf(sqrtf(tot), 1e-12f);
    if (tid == 0) atomicAdd(&g_gnormsq[b], tot * inv * inv);

    float* ob = out + (size_t)b * (Dd * Kk);
#pragma unroll
    for (int p = 0; p < 4; p++) {
        int d = tid + p * 128;
        ob[(size_t)d * Kk + k] = v[p] * inv;
    }
}

// ---------------------------------------------------------------------------
__global__ void k4_scale(float* __restrict__ out)
{
    int idx = blockIdx.x * 256 + threadIdx.x;
    int b = idx >> 15;
    out[idx] *= 1.0f / fmaxf(sqrtf(g_gnormsq[b]), 1e-12f);
}

// ---------------------------------------------------------------------------
extern "C" void kernel_launch(void* const* d_in, const int* in_sizes, int n_in,
                              void* d_out, int out_size)
{
    const float* x        = (const float*)d_in[0];
    const float* clusters = (const float*)d_in[1];
    const float* c2       = (const float*)d_in[2];
    const float* bnw      = (const float*)d_in[3];
    const float* bnb      = (const float*)d_in[4];
    const float* rm       = (const float*)d_in[5];
    const float* rv       = (const float*)d_in[6];
    float* out = (float*)d_out;

    k0_init<<<8, 256>>>();
    k1_logits_softmax<<<(Bb * Nn) / 128, 256>>>(x, clusters, bnw, bnb, rm, rv);
    dim3 g2(Dd / 64, Bb, NSPLIT);
    k2_vlad<<<g2, 128>>>(x);
    k3_colnorm<<<Bb * Kk, 128>>>(c2, out);
    k4_scale<<<(Bb * Dd * Kk) / 256, 256>>>(out);
}